// round 1
// baseline (speedup 1.0000x reference)
#include <cuda_runtime.h>

// ComNet: R=64 runs, T=256 timesteps, N=1024 agents, S=2 sensing dims.
// Wavefront parallelization: cell (t,i) on wavefront f = 2t + i depends only
// on wavefront f-1 (left = c(t,i-1) from own thread, right = c(t-1,i+1) from
// thread t-1). One CTA per run, one thread per timestep.

#define R_ 64
#define T_ 256
#define N_ 1024

__global__ __launch_bounds__(256, 1)
void comnet_kernel(const float* __restrict__ runs,
                   const float* __restrict__ comm0,
                   const float* __restrict__ w1,
                   const float* __restrict__ b1,
                   const float* __restrict__ w2,
                   const float* __restrict__ b2,
                   float* __restrict__ out)
{
    const int r    = blockIdx.x;      // run
    const int t    = threadIdx.x;     // timestep handled by this thread
    const int lane = t & 31;
    const int warp = t >> 5;          // 0..7

    // warp-boundary exchange: value of lane 31 of each warp, double-buffered
    __shared__ float sbuf[2][8];

    // ---- load tiny MLP weights into registers (broadcast loads) ----
    float W1[40], B1[10], W2[20], B2lo, B2hi;
#pragma unroll
    for (int k = 0; k < 40; ++k) W1[k] = w1[k];
#pragma unroll
    for (int k = 0; k < 10; ++k) B1[k] = b1[k];
#pragma unroll
    for (int k = 0; k < 20; ++k) W2[k] = w2[k];
    B2lo = b2[0];
    B2hi = b2[1];

    // per-thread streaming pointers
    const float2* __restrict__ xrow =
        ((const float2*)runs) + ((size_t)r * T_ + t) * N_;          // runs[r,t,:, :]
    float* __restrict__ orow = out + ((size_t)r * T_ + t) * N_;     // out[r,t,:]
    const float* __restrict__ c0row = comm0 + (size_t)r * N_;       // comm0[r,:]

    float c_prev = 0.0f;          // this thread's comm output from previous wavefront
    float4 cbuf = make_float4(0.f, 0.f, 0.f, 0.f);  // control output staging

    const int FMAX = 2 * (T_ - 1) + (N_ - 1);   // 1533

    for (int f = 0; f <= FMAX; ++f) {
        // neighbor (thread t-1) value from wavefront f-1
        float up = __shfl_up_sync(0xffffffffu, c_prev, 1);
        if (lane == 0) {
            // cross-warp: warp w-1 lane 31 wrote at wavefront f-1 into buffer (f-1)&1
            up = sbuf[(f + 1) & 1][(warp > 0) ? (warp - 1) : 0];
        }

        const int i = f - 2 * t;                      // agent index for this thread
        const bool active = ((unsigned)i < (unsigned)N_);

        float cnew = c_prev;
        if (active) {
            const float2 x = xrow[i];
            const float left = (i == 0) ? 0.0f : c_prev;
            float right;
            if (t == 0)
                right = (i < N_ - 1) ? c0row[i + 1] : 0.0f;   // initial comm row
            else
                right = (i < N_ - 1) ? up : 0.0f;             // c(t-1, i+1)

            // ---- MLP: Linear(4,10) -> tanh -> Linear(10,2) ----
            float h[10];
#pragma unroll
            for (int j = 0; j < 10; ++j) {
                float a = B1[j];
                a = fmaf(W1[4 * j + 0], x.x,   a);
                a = fmaf(W1[4 * j + 1], x.y,   a);
                a = fmaf(W1[4 * j + 2], left,  a);
                a = fmaf(W1[4 * j + 3], right, a);
                h[j] = tanhf(a);
            }
            float o0 = B2lo, o1 = B2hi;
#pragma unroll
            for (int j = 0; j < 10; ++j) {
                o0 = fmaf(W2[j],      h[j], o0);
                o1 = fmaf(W2[10 + j], h[j], o1);
            }
            cnew = o1;   // comm update

            // stage control output; flush 16B-aligned float4 every 4 cells
            const int m = i & 3;
            if (m == 0)      cbuf.x = o0;
            else if (m == 1) cbuf.y = o0;
            else if (m == 2) cbuf.z = o0;
            else {
                cbuf.w = o0;
                *(float4*)(orow + (i - 3)) = cbuf;
            }
        }
        c_prev = cnew;
        if (lane == 31) sbuf[f & 1][warp] = cnew;
        __syncthreads();   // orders this wavefront's sbuf writes before next reads
    }
}

extern "C" void kernel_launch(void* const* d_in, const int* in_sizes, int n_in,
                              void* d_out, int out_size)
{
    const float* runs  = (const float*)d_in[0];
    const float* comm0 = (const float*)d_in[1];
    const float* w1    = (const float*)d_in[2];
    const float* b1    = (const float*)d_in[3];
    const float* w2    = (const float*)d_in[4];
    const float* b2    = (const float*)d_in[5];
    float* out = (float*)d_out;

    comnet_kernel<<<R_, T_>>>(runs, comm0, w1, b1, w2, b2, out);
}

// round 2
// speedup vs baseline: 1.5005x; 1.5005x over previous
#include <cuda_runtime.h>

// ComNet: R=64 runs, T=256 timesteps, N=1024 agents.
// Wavefront over blocks of B=4 agents: thread t (one per timestep) computes
// block b = s - 2t at step s. Cell (t,i) needs left=c(t,i-1) (own chain) and
// right=c(t-1,i+1) (neighbor thread, from steps s-1/s-2 -> shuffles + ring).

#define R_ 64
#define T_ 256
#define N_ 1024
#define B_ 4
#define NB_ (N_ / B_)                 // 256 blocks per row
#define NSTEP_ (2 * (T_ - 1) + NB_)   // 766 wavefront steps

__device__ __forceinline__ float fast_rcp(float x) {
    float r;
    asm("rcp.approx.f32 %0, %1;" : "=f"(r) : "f"(x));
    return r;
}

__device__ __forceinline__ float ftanh(float x) {
    // tanh(x) = 1 - 2/(exp(2x)+1); exp via EX2. ~1e-6 rel accuracy, 2 MUFU.
    float e = __expf(2.0f * x);
    return fmaf(-2.0f, fast_rcp(e + 1.0f), 1.0f);
}

__global__ __launch_bounds__(256, 1)
void comnet_kernel(const float* __restrict__ runs,
                   const float* __restrict__ comm0,
                   const float* __restrict__ w1,
                   const float* __restrict__ b1,
                   const float* __restrict__ w2,
                   const float* __restrict__ b2,
                   float* __restrict__ out)
{
    const int r    = blockIdx.x;
    const int t    = threadIdx.x;
    const int lane = t & 31;
    const int warp = t >> 5;

    // 3-deep ring for warp-boundary block exchange (lane31 -> next warp lane0)
    __shared__ float4 ring[3][8];

    // ---- weights in registers ----
    float W1[40], B1[10], W2[20];
#pragma unroll
    for (int k = 0; k < 40; ++k) W1[k] = w1[k];
#pragma unroll
    for (int k = 0; k < 10; ++k) B1[k] = b1[k];
#pragma unroll
    for (int k = 0; k < 20; ++k) W2[k] = w2[k];
    const float B2lo = b2[0];
    const float B2hi = b2[1];

    const float4* __restrict__ xrow4 =
        (const float4*)(runs + ((size_t)r * T_ + t) * (size_t)N_ * 2);
    float4* __restrict__ orow4 = (float4*)(out + ((size_t)r * T_ + t) * N_);
    const float* __restrict__ c0row = comm0 + (size_t)r * N_;

    // h1 = own block from step s-1, h2 = from step s-2
    float4 h1 = make_float4(0.f, 0.f, 0.f, 0.f);
    float4 h2 = h1;

    // prefetch buffers (block b+1's inputs)
    float4 px0 = h1, px1 = h1, pc0 = h1;
    if (t == 0) {   // thread 0 is active at s=0 with b=0
        px0 = xrow4[0];
        px1 = xrow4[1];
        pc0 = make_float4(c0row[1], c0row[2], c0row[3], c0row[4]);
    }

    for (int s = 0; s < NSTEP_; ++s) {
        const int b = s - 2 * t;
        const bool active = ((unsigned)b < (unsigned)NB_);

        // ---- gather right values: c(t-1, 4b+1 .. 4b+4) ----
        float r0, r1, r2, r3;
        {
            // neighbor's h2 elems 1..3 (its block b from step s-2),
            // neighbor's h1 elem 0 (its block b+1 from step s-1)
            float s0 = __shfl_up_sync(0xffffffffu, h2.y, 1);
            float s1 = __shfl_up_sync(0xffffffffu, h2.z, 1);
            float s2 = __shfl_up_sync(0xffffffffu, h2.w, 1);
            float s3 = __shfl_up_sync(0xffffffffu, h1.x, 1);
            if (lane == 0) {
                const int pw = (warp > 0) ? (warp - 1) : 0;
                float4 g2 = ring[(s + 1) % 3][pw];   // (s-2) mod 3
                float4 g1 = ring[(s + 2) % 3][pw];   // (s-1) mod 3
                s0 = g2.y; s1 = g2.z; s2 = g2.w; s3 = g1.x;
            }
            r0 = s0; r1 = s1; r2 = s2; r3 = s3;
        }
        if (t == 0) { r0 = pc0.x; r1 = pc0.y; r2 = pc0.z; r3 = pc0.w; }
        if (b == NB_ - 1) r3 = 0.0f;     // agent N-1 has zero right boundary

        // current block inputs (prefetched last step)
        const float4 cx0 = px0, cx1 = px1;

        // ---- prefetch next block's inputs ----
        const int bn = s + 1 - 2 * t;
        if ((unsigned)bn < (unsigned)NB_) {
            px0 = xrow4[2 * bn];
            px1 = xrow4[2 * bn + 1];
            if (t == 0) {
                const int base = 4 * bn;
                pc0 = make_float4(c0row[base + 1], c0row[base + 2],
                                  c0row[base + 3],
                                  (bn < NB_ - 1) ? c0row[base + 4] : 0.0f);
            }
        }

        float4 cur = h1;
        if (active) {
            float o0v[4], o1v[4];
            float lf = (b == 0) ? 0.0f : h1.w;   // c(t, 4b-1)
#pragma unroll
            for (int k = 0; k < 4; ++k) {
                const float xx = (k == 0) ? cx0.x : (k == 1) ? cx0.z
                                : (k == 2) ? cx1.x : cx1.z;
                const float xy = (k == 0) ? cx0.y : (k == 1) ? cx0.w
                                : (k == 2) ? cx1.y : cx1.w;
                const float rt = (k == 0) ? r0 : (k == 1) ? r1
                                : (k == 2) ? r2 : r3;

                float a0 = B2lo, a0b = 0.f, a1 = B2hi, a1b = 0.f;
#pragma unroll
                for (int j = 0; j < 10; ++j) {
                    float a = fmaf(W1[4 * j],     xx, B1[j]);
                    a       = fmaf(W1[4 * j + 1], xy, a);
                    a       = fmaf(W1[4 * j + 2], lf, a);
                    a       = fmaf(W1[4 * j + 3], rt, a);
                    const float h = ftanh(a);
                    if (j & 1) { a0b = fmaf(W2[j], h, a0b); a1b = fmaf(W2[10 + j], h, a1b); }
                    else       { a0  = fmaf(W2[j], h, a0);  a1  = fmaf(W2[10 + j], h, a1); }
                }
                o0v[k] = a0 + a0b;
                const float o1 = a1 + a1b;
                o1v[k] = o1;
                lf = o1;                         // chain left within block
            }
            orow4[b] = make_float4(o0v[0], o0v[1], o0v[2], o0v[3]);
            cur = make_float4(o1v[0], o1v[1], o1v[2], o1v[3]);
        }

        // shift history; publish warp-boundary block
        h2 = h1;
        if (active) h1 = cur;
        if (lane == 31 && active) ring[s % 3][warp] = cur;
        __syncthreads();
    }
}

extern "C" void kernel_launch(void* const* d_in, const int* in_sizes, int n_in,
                              void* d_out, int out_size)
{
    const float* runs  = (const float*)d_in[0];
    const float* comm0 = (const float*)d_in[1];
    const float* w1    = (const float*)d_in[2];
    const float* b1    = (const float*)d_in[3];
    const float* w2    = (const float*)d_in[4];
    const float* b2    = (const float*)d_in[5];
    float* out = (float*)d_out;

    comnet_kernel<<<R_, T_>>>(runs, comm0, w1, b1, w2, b2, out);
}